// round 15
// baseline (speedup 1.0000x reference)
#include <cuda_runtime.h>
#include <cuda_fp16.h>
#include <cstdint>

// Problem constants: N=8192, D=512, OUT=1
#define NROWS 8192
#define DDIM  512
#define KBIG  1024            // logical concat K: [hi | residual] (A dedups to 512)
#define BK    64              // fp16 per K-chunk = 128 bytes/row
#define NCHUNK (KBIG / BK)    // 16
#define STAGE_BYTES 49152     // A 128x64x2 = 16KB + B 256x64x2 = 32KB
#define SMEM_TOTAL (3 * STAGE_BYTES)   // 147456
#define TPITCH 132            // fp32 pitch for epilogue transpose buffer

// Scratch in __device__ globals (no allocations allowed)
__device__ __half g_X[(size_t)NROWS * KBIG];  // [xh | xl]   (xl = fp16(x - xh))
__device__ __half g_Y[(size_t)NROWS * DDIM];  // yh only (A loader wraps k0 & 511)
__device__ float g_d[NROWS];

// ---------------- helpers ----------------
__device__ __forceinline__ uint32_t smem_u32(const void* p) {
    uint32_t a;
    asm("{ .reg .u64 t; cvta.to.shared.u64 t, %1; cvt.u32.u64 %0, t; }" : "=r"(a) : "l"(p));
    return a;
}
__device__ __forceinline__ void cpa16(uint32_t s, const void* g) {
    asm volatile("cp.async.cg.shared.global [%0], [%1], 16;"
                 :: "r"(s), "l"(__cvta_generic_to_global(g)) : "memory");
}
#define SWZ(o) ((o) ^ (((o) >> 3) & 0x70))

__device__ __forceinline__ void ldsm_x4(uint32_t* r, uint32_t addr) {
    asm volatile("ldmatrix.sync.aligned.m8n8.x4.shared.b16 {%0,%1,%2,%3}, [%4];"
                 : "=r"(r[0]), "=r"(r[1]), "=r"(r[2]), "=r"(r[3]) : "r"(addr));
}
__device__ __forceinline__ void mma16816(float* c, const uint32_t* a, uint32_t b0, uint32_t b1) {
    asm volatile("mma.sync.aligned.m16n8k16.row.col.f32.f16.f16.f32 "
                 "{%0,%1,%2,%3}, {%4,%5,%6,%7}, {%8,%9}, {%0,%1,%2,%3};"
                 : "+f"(c[0]), "+f"(c[1]), "+f"(c[2]), "+f"(c[3])
                 : "r"(a[0]), "r"(a[1]), "r"(a[2]), "r"(a[3]), "r"(b0), "r"(b1));
}

// ---------------------------------------------------------------------------
// Kernel 1: one warp per row — mu, softplus d, split-fp16 operand build.
//   g_Y[i] = yh,  g_X[i] = [xh | xl],  y = x * rho
// ---------------------------------------------------------------------------
__global__ void prep_kernel(const float* __restrict__ x,
                            const float* __restrict__ mu_k,
                            const float* __restrict__ rho,
                            const float* __restrict__ var_k,
                            const float* __restrict__ mu_b,
                            const float* __restrict__ var_b,
                            float* __restrict__ mu_out) {
    int row  = (int)((blockIdx.x * blockDim.x + threadIdx.x) >> 5);
    int lane = threadIdx.x & 31;
    if (row >= NROWS) return;

    const float* xr = x + (size_t)row * DDIM;
    __half* Xr = g_X + (size_t)row * KBIG;
    __half* Yr = g_Y + (size_t)row * DDIM;

    float smu = 0.f, sv = 0.f;
#pragma unroll
    for (int k = lane; k < DDIM; k += 32) {
        float xv = xr[k];
        smu = fmaf(xv, mu_k[k], smu);
        sv  = fmaf(xv, var_k[k], sv);
        float yv = xv * rho[k];

        __half xh = __float2half_rn(xv);
        __half xl = __float2half_rn(xv - __half2float(xh));

        Xr[k] = xh; Xr[DDIM + k] = xl;
        Yr[k] = __float2half_rn(yv);
    }
#pragma unroll
    for (int o = 16; o > 0; o >>= 1) {
        smu += __shfl_down_sync(0xffffffffu, smu, o);
        sv  += __shfl_down_sync(0xffffffffu, sv,  o);
    }
    if (lane == 0) {
        mu_out[row] = smu + mu_b[0];
        float z  = sv + var_b[0];
        float sp = (z > 20.f) ? z : log1pf(expf(z));
        g_d[row] = sp + 1e-8f;
    }
}

// ---------------------------------------------------------------------------
// Kernel 2: fp16 HMMA GEMM, block tile 128x256, warp tile 64x64 (8 warps),
// K=1024 (A wraps at 512), 3-stage cp.async pipeline, register-level fragment
// double-buffering, triangular grid (r <= 2c+1). Straddle tiles fuse the
// diagonal overwrite and skip the mirror; one writer per output element.
// ---------------------------------------------------------------------------
__global__ __launch_bounds__(256, 1)
void cov_gemm_mma(float* __restrict__ C, const float* __restrict__ cov_b) {
    extern __shared__ char smem[];
    const uint32_t sb = smem_u32(smem);
    const int tid  = threadIdx.x;
    const int wid  = tid >> 5;
    const int lane = tid & 31;
    const int wm   = wid & 1;    // m offset wm*64
    const int wn   = wid >> 1;   // n offset wn*64

    // blockIdx -> (r, c): b = c(c+1) + r, r in [0, 2c+2)
    int b = blockIdx.x;
    int c = (int)((sqrtf(4.0f * (float)b + 1.0f) - 1.0f) * 0.5f);
    while ((c + 1) * (c + 2) <= b) c++;
    while (c * (c + 1) > b) c--;
    const int r  = b - c * (c + 1);
    const int i0 = r << 7;   // 128-row tile
    const int j0 = c << 8;   // 256-col tile

    const __half* Ab = g_Y + (size_t)i0 * DDIM;
    const __half* Bb = g_X + (size_t)j0 * KBIG;

    float acc[4][8][4];
#pragma unroll
    for (int mt = 0; mt < 4; mt++)
#pragma unroll
        for (int nt = 0; nt < 8; nt++)
#pragma unroll
            for (int q = 0; q < 4; q++) acc[mt][nt][q] = 0.f;

    // ---- stage loader: A 1024 vec16 + B 2048 vec16 = 12 per thread ----
    auto load_stage = [&](int s, int kt) {
        const int k0 = kt * BK;
        const int k0a = k0 & (DDIM - 1);      // A dedup: [yh|yh] -> wrap
        const uint32_t sA = sb + s * STAGE_BYTES;
        const uint32_t sB = sA + 16384;
#pragma unroll
        for (int v = 0; v < 12; v++) {
            int e = tid + v * 256;
            if (e < 1024) {
                int row = e >> 3, c16 = e & 7;
                cpa16(sA + SWZ(row * 128 + c16 * 16),
                      Ab + (size_t)row * DDIM + k0a + c16 * 8);
            } else {
                int eb = e - 1024;
                int row = eb >> 3, c16 = eb & 7;
                cpa16(sB + SWZ(row * 128 + c16 * 16),
                      Bb + (size_t)row * KBIG + k0 + c16 * 8);
            }
        }
    };

    // ---- prologue: 2 stages in flight ----
    load_stage(0, 0);
    asm volatile("cp.async.commit_group;" ::: "memory");
    load_stage(1, 1);
    asm volatile("cp.async.commit_group;" ::: "memory");

    // ldmatrix lane addressing
    const int a_row = lane & 15;
    const int a_kb  = (lane >> 4) * 16;
    const int b_g   = lane >> 3;
    const int b_r   = lane & 7;
    const int b_row = ((b_g >> 1) * 8) + b_r;
    const int b_kb  = (b_g & 1) * 16;

    // ---- main loop with register fragment double-buffering ----
    uint32_t afr[2][4][4], bfr[2][4][4];
    int scur = 0, sload = 2;
    for (int kt = 0; kt < NCHUNK; kt++) {
        asm volatile("cp.async.wait_group 1;" ::: "memory");
        __syncthreads();

        if (kt + 2 < NCHUNK) load_stage(sload, kt + 2);
        asm volatile("cp.async.commit_group;" ::: "memory");

        const uint32_t sA = sb + scur * STAGE_BYTES;
        const uint32_t sB = sA + 16384;

        // prefetch kk=0 fragments
#pragma unroll
        for (int mt = 0; mt < 4; mt++)
            ldsm_x4(afr[0][mt], sA + SWZ((wm * 64 + mt * 16 + a_row) * 128 + a_kb));
#pragma unroll
        for (int q = 0; q < 4; q++)
            ldsm_x4(bfr[0][q], sB + SWZ((wn * 64 + q * 16 + b_row) * 128 + b_kb));

#pragma unroll
        for (int kk = 0; kk < 4; kk++) {
            const int cur = kk & 1, nxt = cur ^ 1;
            if (kk < 3) {   // prefetch kk+1 while kk's MMAs issue
#pragma unroll
                for (int mt = 0; mt < 4; mt++)
                    ldsm_x4(afr[nxt][mt],
                            sA + SWZ((wm * 64 + mt * 16 + a_row) * 128 + (kk + 1) * 32 + a_kb));
#pragma unroll
                for (int q = 0; q < 4; q++)
                    ldsm_x4(bfr[nxt][q],
                            sB + SWZ((wn * 64 + q * 16 + b_row) * 128 + (kk + 1) * 32 + b_kb));
            }
#pragma unroll
            for (int mt = 0; mt < 4; mt++)
#pragma unroll
                for (int nt = 0; nt < 8; nt++) {
                    int q = nt >> 1, h = nt & 1;
                    mma16816(acc[mt][nt], afr[cur][mt], bfr[cur][q][2 * h], bfr[cur][q][2 * h + 1]);
                }
        }
        scur = (scur == 2) ? 0 : scur + 1;
        sload = (sload == 2) ? 0 : sload + 1;
    }
    asm volatile("cp.async.wait_group 0;" ::: "memory");
    __syncthreads();   // pipeline drained; smem reusable for transpose

    // ---- epilogue ----
    const float cb = cov_b[0];
    const int g4 = lane >> 2;
    const int t2 = lane & 3;
    const bool straddle = ((r >> 1) == c);   // tile contains the diagonal band

    float* st = (float*)smem;   // 256 x TPITCH transpose buffer (j-major)

#pragma unroll
    for (int mt = 0; mt < 4; mt++)
#pragma unroll
        for (int nt = 0; nt < 8; nt++) {
            int il = wm * 64 + mt * 16 + g4;
            int jl = wn * 64 + nt * 8 + t2 * 2;
            float v0 = acc[mt][nt][0] + cb;
            float v1 = acc[mt][nt][1] + cb;
            float v2 = acc[mt][nt][2] + cb;
            float v3 = acc[mt][nt][3] + cb;

            if (straddle) {   // fused diagonal overwrite (all diag cells live here)
                int gi = i0 + il, gj = j0 + jl;
                if (gi == gj)         v0 = g_d[gi];
                if (gi == gj + 1)     v1 = g_d[gi];
                if (gi + 8 == gj)     v2 = g_d[gi + 8];
                if (gi + 8 == gj + 1) v3 = g_d[gi + 8];
            }

            size_t o0 = (size_t)(i0 + il) * NROWS + (j0 + jl);
            size_t o1 = (size_t)(i0 + il + 8) * NROWS + (j0 + jl);
            *(float2*)(C + o0) = make_float2(v0, v1);
            *(float2*)(C + o1) = make_float2(v2, v3);

            if (!straddle) {
                st[(jl + 0) * TPITCH + il]     = v0;
                st[(jl + 1) * TPITCH + il]     = v1;
                st[(jl + 0) * TPITCH + il + 8] = v2;
                st[(jl + 1) * TPITCH + il + 8] = v3;
            }
        }

    if (!straddle) {   // mirror 256x128 transposed block into the lower triangle
        __syncthreads();
#pragma unroll
        for (int it = 0; it < 32; it++) {
            int jj = it * 8 + wid;
            float4 v = *(float4*)(st + jj * TPITCH + lane * 4);
            *(float4*)(C + (size_t)(j0 + jj) * NROWS + i0 + lane * 4) = v;
        }
    }
}

// ---------------------------------------------------------------------------
extern "C" void kernel_launch(void* const* d_in, const int* in_sizes, int n_in,
                              void* d_out, int out_size) {
    (void)in_sizes; (void)n_in; (void)out_size;
    const float* x     = (const float*)d_in[0];
    const float* mu_k  = (const float*)d_in[1];
    const float* rho   = (const float*)d_in[2];
    const float* var_k = (const float*)d_in[3];
    const float* mu_b  = (const float*)d_in[4];
    const float* var_b = (const float*)d_in[5];
    const float* cov_b = (const float*)d_in[6];

    float* out = (float*)d_out;
    float* mu  = out;
    float* cov = out + NROWS;

    cudaFuncSetAttribute(cov_gemm_mma, cudaFuncAttributeMaxDynamicSharedMemorySize, SMEM_TOTAL);

    prep_kernel<<<NROWS / 8, 256>>>(x, mu_k, rho, var_k, mu_b, var_b, mu);

    // 1056 = sum_{c=0}^{31} (2c+2) upper-cover 128x256 tiles
    cov_gemm_mma<<<1056, 256, SMEM_TOTAL>>>(cov, cov_b);
}

// round 16
// speedup vs baseline: 1.1358x; 1.1358x over previous
#include <cuda_runtime.h>
#include <cuda_fp16.h>
#include <cstdint>

// Problem constants: N=8192, D=512, OUT=1
#define NROWS 8192
#define DDIM  512
#define KBIG  1024            // logical concat K: [hi | residual] (A dedups to 512)
#define BK    64              // fp16 per K-chunk = 128 bytes/row
#define NCHUNK (KBIG / BK)    // 16
#define STAGE_BYTES 32768     // A 128x64x2 = 16KB + B 128x64x2 = 16KB
#define SMEM_TOTAL (3 * STAGE_BYTES)   // 98304 -> 2 CTAs/SM fit (192KB)
#define TPITCH 132            // fp32 pitch for epilogue transpose buffer

// Scratch in __device__ globals (no allocations allowed)
__device__ __half g_X[(size_t)NROWS * KBIG];  // [xh | xl]   (xl = fp16(x - xh))
__device__ __half g_Y[(size_t)NROWS * DDIM];  // yh only (A loader wraps k0 & 511)
__device__ float g_d[NROWS];

// ---------------- helpers ----------------
__device__ __forceinline__ uint32_t smem_u32(const void* p) {
    uint32_t a;
    asm("{ .reg .u64 t; cvta.to.shared.u64 t, %1; cvt.u32.u64 %0, t; }" : "=r"(a) : "l"(p));
    return a;
}
__device__ __forceinline__ void cpa16(uint32_t s, const void* g) {
    asm volatile("cp.async.cg.shared.global [%0], [%1], 16;"
                 :: "r"(s), "l"(__cvta_generic_to_global(g)) : "memory");
}
#define SWZ(o) ((o) ^ (((o) >> 3) & 0x70))

__device__ __forceinline__ void ldsm_x4(uint32_t* r, uint32_t addr) {
    asm volatile("ldmatrix.sync.aligned.m8n8.x4.shared.b16 {%0,%1,%2,%3}, [%4];"
                 : "=r"(r[0]), "=r"(r[1]), "=r"(r[2]), "=r"(r[3]) : "r"(addr));
}
__device__ __forceinline__ void mma16816(float* c, const uint32_t* a, uint32_t b0, uint32_t b1) {
    asm volatile("mma.sync.aligned.m16n8k16.row.col.f32.f16.f16.f32 "
                 "{%0,%1,%2,%3}, {%4,%5,%6,%7}, {%8,%9}, {%0,%1,%2,%3};"
                 : "+f"(c[0]), "+f"(c[1]), "+f"(c[2]), "+f"(c[3])
                 : "r"(a[0]), "r"(a[1]), "r"(a[2]), "r"(a[3]), "r"(b0), "r"(b1));
}

// ---------------------------------------------------------------------------
// Kernel 1: one warp per row — mu, softplus d, split-fp16 operand build.
//   g_Y[i] = yh,  g_X[i] = [xh | xl],  y = x * rho
// ---------------------------------------------------------------------------
__global__ void prep_kernel(const float* __restrict__ x,
                            const float* __restrict__ mu_k,
                            const float* __restrict__ rho,
                            const float* __restrict__ var_k,
                            const float* __restrict__ mu_b,
                            const float* __restrict__ var_b,
                            float* __restrict__ mu_out) {
    int row  = (int)((blockIdx.x * blockDim.x + threadIdx.x) >> 5);
    int lane = threadIdx.x & 31;
    if (row >= NROWS) return;

    const float* xr = x + (size_t)row * DDIM;
    __half* Xr = g_X + (size_t)row * KBIG;
    __half* Yr = g_Y + (size_t)row * DDIM;

    float smu = 0.f, sv = 0.f;
#pragma unroll
    for (int k = lane; k < DDIM; k += 32) {
        float xv = xr[k];
        smu = fmaf(xv, mu_k[k], smu);
        sv  = fmaf(xv, var_k[k], sv);
        float yv = xv * rho[k];

        __half xh = __float2half_rn(xv);
        __half xl = __float2half_rn(xv - __half2float(xh));

        Xr[k] = xh; Xr[DDIM + k] = xl;
        Yr[k] = __float2half_rn(yv);
    }
#pragma unroll
    for (int o = 16; o > 0; o >>= 1) {
        smu += __shfl_down_sync(0xffffffffu, smu, o);
        sv  += __shfl_down_sync(0xffffffffu, sv,  o);
    }
    if (lane == 0) {
        mu_out[row] = smu + mu_b[0];
        float z  = sv + var_b[0];
        float sp = (z > 20.f) ? z : log1pf(expf(z));
        g_d[row] = sp + 1e-8f;
    }
}

// ---------------------------------------------------------------------------
// Kernel 2: fp16 HMMA GEMM, block tile 128x128, 4 warps (64x64 warp tiles),
// 2 CTAs/SM. K=1024 (A wraps at 512), 3-stage cp.async pipeline, fragment
// double-buffering, triangular grid (r <= c over 128x128 tiles).
// Diagonal tiles (r == c) fuse the diag overwrite and skip the mirror.
// ---------------------------------------------------------------------------
__global__ __launch_bounds__(128, 2)
void cov_gemm_mma(float* __restrict__ C, const float* __restrict__ cov_b) {
    extern __shared__ char smem[];
    const uint32_t sb = smem_u32(smem);
    const int tid  = threadIdx.x;
    const int wid  = tid >> 5;
    const int lane = tid & 31;
    const int wm   = wid & 1;    // m offset wm*64
    const int wn   = wid >> 1;   // n offset wn*64

    // blockIdx -> (r, c): b = c(c+1)/2 + r, r <= c
    int b = blockIdx.x;
    int c = (int)((sqrtf(8.0f * (float)b + 1.0f) - 1.0f) * 0.5f);
    while ((c + 1) * (c + 2) / 2 <= b) c++;
    while (c * (c + 1) / 2 > b) c--;
    const int r  = b - c * (c + 1) / 2;
    const int i0 = r << 7;
    const int j0 = c << 7;

    const __half* Ab = g_Y + (size_t)i0 * DDIM;
    const __half* Bb = g_X + (size_t)j0 * KBIG;

    float acc[4][8][4];
#pragma unroll
    for (int mt = 0; mt < 4; mt++)
#pragma unroll
        for (int nt = 0; nt < 8; nt++)
#pragma unroll
            for (int q = 0; q < 4; q++) acc[mt][nt][q] = 0.f;

    // ---- stage loader: A 1024 + B 1024 vec16 = 16 per thread ----
    auto load_stage = [&](int s, int kt) {
        const int k0 = kt * BK;
        const int k0a = k0 & (DDIM - 1);      // A dedup: [yh|yh] -> wrap
        const uint32_t sA = sb + s * STAGE_BYTES;
        const uint32_t sB = sA + 16384;
#pragma unroll
        for (int v = 0; v < 16; v++) {
            int e = tid + v * 128;
            if (e < 1024) {
                int row = e >> 3, c16 = e & 7;
                cpa16(sA + SWZ(row * 128 + c16 * 16),
                      Ab + (size_t)row * DDIM + k0a + c16 * 8);
            } else {
                int eb = e - 1024;
                int row = eb >> 3, c16 = eb & 7;
                cpa16(sB + SWZ(row * 128 + c16 * 16),
                      Bb + (size_t)row * KBIG + k0 + c16 * 8);
            }
        }
    };

    // ---- prologue: 2 stages in flight ----
    load_stage(0, 0);
    asm volatile("cp.async.commit_group;" ::: "memory");
    load_stage(1, 1);
    asm volatile("cp.async.commit_group;" ::: "memory");

    // ldmatrix lane addressing
    const int a_row = lane & 15;
    const int a_kb  = (lane >> 4) * 16;
    const int b_g   = lane >> 3;
    const int b_r   = lane & 7;
    const int b_row = ((b_g >> 1) * 8) + b_r;
    const int b_kb  = (b_g & 1) * 16;

    // ---- main loop with register fragment double-buffering ----
    uint32_t afr[2][4][4], bfr[2][4][4];
    int scur = 0, sload = 2;
    for (int kt = 0; kt < NCHUNK; kt++) {
        asm volatile("cp.async.wait_group 1;" ::: "memory");
        __syncthreads();

        if (kt + 2 < NCHUNK) load_stage(sload, kt + 2);
        asm volatile("cp.async.commit_group;" ::: "memory");

        const uint32_t sA = sb + scur * STAGE_BYTES;
        const uint32_t sB = sA + 16384;

        // prefetch kk=0 fragments
#pragma unroll
        for (int mt = 0; mt < 4; mt++)
            ldsm_x4(afr[0][mt], sA + SWZ((wm * 64 + mt * 16 + a_row) * 128 + a_kb));
#pragma unroll
        for (int q = 0; q < 4; q++)
            ldsm_x4(bfr[0][q], sB + SWZ((wn * 64 + q * 16 + b_row) * 128 + b_kb));

#pragma unroll
        for (int kk = 0; kk < 4; kk++) {
            const int cur = kk & 1, nxt = cur ^ 1;
            if (kk < 3) {   // prefetch kk+1 while kk's MMAs issue
#pragma unroll
                for (int mt = 0; mt < 4; mt++)
                    ldsm_x4(afr[nxt][mt],
                            sA + SWZ((wm * 64 + mt * 16 + a_row) * 128 + (kk + 1) * 32 + a_kb));
#pragma unroll
                for (int q = 0; q < 4; q++)
                    ldsm_x4(bfr[nxt][q],
                            sB + SWZ((wn * 64 + q * 16 + b_row) * 128 + (kk + 1) * 32 + b_kb));
            }
#pragma unroll
            for (int mt = 0; mt < 4; mt++)
#pragma unroll
                for (int nt = 0; nt < 8; nt++) {
                    int q = nt >> 1, h = nt & 1;
                    mma16816(acc[mt][nt], afr[cur][mt], bfr[cur][q][2 * h], bfr[cur][q][2 * h + 1]);
                }
        }
        scur = (scur == 2) ? 0 : scur + 1;
        sload = (sload == 2) ? 0 : sload + 1;
    }
    asm volatile("cp.async.wait_group 0;" ::: "memory");
    __syncthreads();   // pipeline drained; smem reusable for transpose

    // ---- epilogue ----
    const float cb = cov_b[0];
    const int g4 = lane >> 2;
    const int t2 = lane & 3;
    const bool diag = (r == c);

    float* st = (float*)smem;   // 128 x TPITCH transpose buffer (j-major)

#pragma unroll
    for (int mt = 0; mt < 4; mt++)
#pragma unroll
        for (int nt = 0; nt < 8; nt++) {
            int il = wm * 64 + mt * 16 + g4;
            int jl = wn * 64 + nt * 8 + t2 * 2;
            float v0 = acc[mt][nt][0] + cb;
            float v1 = acc[mt][nt][1] + cb;
            float v2 = acc[mt][nt][2] + cb;
            float v3 = acc[mt][nt][3] + cb;

            if (diag) {   // fused diagonal overwrite
                if (il == jl)         v0 = g_d[i0 + il];
                if (il == jl + 1)     v1 = g_d[i0 + il];
                if (il + 8 == jl)     v2 = g_d[i0 + il + 8];
                if (il + 8 == jl + 1) v3 = g_d[i0 + il + 8];
            }

            size_t o0 = (size_t)(i0 + il) * NROWS + (j0 + jl);
            size_t o1 = (size_t)(i0 + il + 8) * NROWS + (j0 + jl);
            *(float2*)(C + o0) = make_float2(v0, v1);
            *(float2*)(C + o1) = make_float2(v2, v3);

            if (!diag) {
                st[(jl + 0) * TPITCH + il]     = v0;
                st[(jl + 1) * TPITCH + il]     = v1;
                st[(jl + 0) * TPITCH + il + 8] = v2;
                st[(jl + 1) * TPITCH + il + 8] = v3;
            }
        }

    if (!diag) {   // mirror 128x128 transposed block into the lower triangle
        __syncthreads();
#pragma unroll
        for (int it = 0; it < 32; it++) {
            int jj = it * 4 + wid;
            float4 v = *(float4*)(st + jj * TPITCH + lane * 4);
            *(float4*)(C + (size_t)(j0 + jj) * NROWS + i0 + lane * 4) = v;
        }
    }
}

// ---------------------------------------------------------------------------
extern "C" void kernel_launch(void* const* d_in, const int* in_sizes, int n_in,
                              void* d_out, int out_size) {
    (void)in_sizes; (void)n_in; (void)out_size;
    const float* x     = (const float*)d_in[0];
    const float* mu_k  = (const float*)d_in[1];
    const float* rho   = (const float*)d_in[2];
    const float* var_k = (const float*)d_in[3];
    const float* mu_b  = (const float*)d_in[4];
    const float* var_b = (const float*)d_in[5];
    const float* cov_b = (const float*)d_in[6];

    float* out = (float*)d_out;
    float* mu  = out;
    float* cov = out + NROWS;

    cudaFuncSetAttribute(cov_gemm_mma, cudaFuncAttributeMaxDynamicSharedMemorySize, SMEM_TOTAL);

    prep_kernel<<<NROWS / 8, 256>>>(x, mu_k, rho, var_k, mu_b, var_b, mu);

    // 2080 = 64*65/2 upper-triangular 128x128 tiles (incl. diagonal)
    cov_gemm_mma<<<2080, 128, SMEM_TOTAL>>>(cov, cov_b);
}

// round 17
// speedup vs baseline: 1.7385x; 1.5307x over previous
#include <cuda_runtime.h>
#include <cuda_fp16.h>
#include <cstdint>

// Problem constants: N=8192, D=512, OUT=1
#define NROWS 8192
#define DDIM  512
#define KDIM  512             // single-term fp16 GEMM: yh @ xh^T
#define BK    64              // fp16 per K-chunk = 128 bytes/row
#define NCHUNK (KDIM / BK)    // 8
#define STAGE_BYTES 32768     // A 128x64x2 = 16KB + B 128x64x2 = 16KB
#define SMEM_TOTAL (3 * STAGE_BYTES)   // 98304 -> 2 CTAs/SM (192KB)
#define TPITCH 132            // fp32 pitch for epilogue transpose buffer

// Scratch in __device__ globals (no allocations allowed)
__device__ __half g_X[(size_t)NROWS * KDIM];  // xh = fp16(x)
__device__ __half g_Y[(size_t)NROWS * KDIM];  // yh = fp16(x * rho)
__device__ float g_d[NROWS];

// ---------------- helpers ----------------
__device__ __forceinline__ uint32_t smem_u32(const void* p) {
    uint32_t a;
    asm("{ .reg .u64 t; cvta.to.shared.u64 t, %1; cvt.u32.u64 %0, t; }" : "=r"(a) : "l"(p));
    return a;
}
__device__ __forceinline__ void cpa16(uint32_t s, const void* g) {
    asm volatile("cp.async.cg.shared.global [%0], [%1], 16;"
                 :: "r"(s), "l"(__cvta_generic_to_global(g)) : "memory");
}
#define SWZ(o) ((o) ^ (((o) >> 3) & 0x70))

__device__ __forceinline__ void ldsm_x4(uint32_t* r, uint32_t addr) {
    asm volatile("ldmatrix.sync.aligned.m8n8.x4.shared.b16 {%0,%1,%2,%3}, [%4];"
                 : "=r"(r[0]), "=r"(r[1]), "=r"(r[2]), "=r"(r[3]) : "r"(addr));
}
__device__ __forceinline__ void mma16816(float* c, const uint32_t* a, uint32_t b0, uint32_t b1) {
    asm volatile("mma.sync.aligned.m16n8k16.row.col.f32.f16.f16.f32 "
                 "{%0,%1,%2,%3}, {%4,%5,%6,%7}, {%8,%9}, {%0,%1,%2,%3};"
                 : "+f"(c[0]), "+f"(c[1]), "+f"(c[2]), "+f"(c[3])
                 : "r"(a[0]), "r"(a[1]), "r"(a[2]), "r"(a[3]), "r"(b0), "r"(b1));
}

// ---------------------------------------------------------------------------
// Kernel 1: one warp per row — mu, softplus d, fp16 operand build.
// ---------------------------------------------------------------------------
__global__ void prep_kernel(const float* __restrict__ x,
                            const float* __restrict__ mu_k,
                            const float* __restrict__ rho,
                            const float* __restrict__ var_k,
                            const float* __restrict__ mu_b,
                            const float* __restrict__ var_b,
                            float* __restrict__ mu_out) {
    int row  = (int)((blockIdx.x * blockDim.x + threadIdx.x) >> 5);
    int lane = threadIdx.x & 31;
    if (row >= NROWS) return;

    const float* xr = x + (size_t)row * DDIM;
    __half* Xr = g_X + (size_t)row * KDIM;
    __half* Yr = g_Y + (size_t)row * KDIM;

    float smu = 0.f, sv = 0.f;
#pragma unroll
    for (int k = lane; k < DDIM; k += 32) {
        float xv = xr[k];
        smu = fmaf(xv, mu_k[k], smu);
        sv  = fmaf(xv, var_k[k], sv);
        Xr[k] = __float2half_rn(xv);
        Yr[k] = __float2half_rn(xv * rho[k]);
    }
#pragma unroll
    for (int o = 16; o > 0; o >>= 1) {
        smu += __shfl_down_sync(0xffffffffu, smu, o);
        sv  += __shfl_down_sync(0xffffffffu, sv,  o);
    }
    if (lane == 0) {
        mu_out[row] = smu + mu_b[0];
        float z  = sv + var_b[0];
        float sp = (z > 20.f) ? z : log1pf(expf(z));
        g_d[row] = sp + 1e-8f;
    }
}

// ---------------------------------------------------------------------------
// Kernel 2: fp16 HMMA GEMM, block tile 128x128, 4 warps (64x64 warp tiles),
// 2 CTAs/SM. K=512, 3-stage cp.async pipeline, fragment double-buffering,
// triangular grid (r <= c). Diagonal tiles fuse diag overwrite, skip mirror.
// ---------------------------------------------------------------------------
__global__ __launch_bounds__(128, 2)
void cov_gemm_mma(float* __restrict__ C, const float* __restrict__ cov_b) {
    extern __shared__ char smem[];
    const uint32_t sb = smem_u32(smem);
    const int tid  = threadIdx.x;
    const int wid  = tid >> 5;
    const int lane = tid & 31;
    const int wm   = wid & 1;    // m offset wm*64
    const int wn   = wid >> 1;   // n offset wn*64

    // blockIdx -> (r, c): b = c(c+1)/2 + r, r <= c
    int b = blockIdx.x;
    int c = (int)((sqrtf(8.0f * (float)b + 1.0f) - 1.0f) * 0.5f);
    while ((c + 1) * (c + 2) / 2 <= b) c++;
    while (c * (c + 1) / 2 > b) c--;
    const int r  = b - c * (c + 1) / 2;
    const int i0 = r << 7;
    const int j0 = c << 7;

    const __half* Ab = g_Y + (size_t)i0 * KDIM;
    const __half* Bb = g_X + (size_t)j0 * KDIM;

    float acc[4][8][4];
#pragma unroll
    for (int mt = 0; mt < 4; mt++)
#pragma unroll
        for (int nt = 0; nt < 8; nt++)
#pragma unroll
            for (int q = 0; q < 4; q++) acc[mt][nt][q] = 0.f;

    // ---- stage loader: A 1024 + B 1024 vec16 = 16 per thread ----
    auto load_stage = [&](int s, int kt) {
        const int k0 = kt * BK;
        const uint32_t sA = sb + s * STAGE_BYTES;
        const uint32_t sB = sA + 16384;
#pragma unroll
        for (int v = 0; v < 16; v++) {
            int e = tid + v * 128;
            if (e < 1024) {
                int row = e >> 3, c16 = e & 7;
                cpa16(sA + SWZ(row * 128 + c16 * 16),
                      Ab + (size_t)row * KDIM + k0 + c16 * 8);
            } else {
                int eb = e - 1024;
                int row = eb >> 3, c16 = eb & 7;
                cpa16(sB + SWZ(row * 128 + c16 * 16),
                      Bb + (size_t)row * KDIM + k0 + c16 * 8);
            }
        }
    };

    // ---- prologue: 2 stages in flight ----
    load_stage(0, 0);
    asm volatile("cp.async.commit_group;" ::: "memory");
    load_stage(1, 1);
    asm volatile("cp.async.commit_group;" ::: "memory");

    // ldmatrix lane addressing
    const int a_row = lane & 15;
    const int a_kb  = (lane >> 4) * 16;
    const int b_g   = lane >> 3;
    const int b_r   = lane & 7;
    const int b_row = ((b_g >> 1) * 8) + b_r;
    const int b_kb  = (b_g & 1) * 16;

    // ---- main loop with register fragment double-buffering ----
    uint32_t afr[2][4][4], bfr[2][4][4];
    int scur = 0, sload = 2;
    for (int kt = 0; kt < NCHUNK; kt++) {
        asm volatile("cp.async.wait_group 1;" ::: "memory");
        __syncthreads();

        if (kt + 2 < NCHUNK) load_stage(sload, kt + 2);
        asm volatile("cp.async.commit_group;" ::: "memory");

        const uint32_t sA = sb + scur * STAGE_BYTES;
        const uint32_t sB = sA + 16384;

        // prefetch kk=0 fragments
#pragma unroll
        for (int mt = 0; mt < 4; mt++)
            ldsm_x4(afr[0][mt], sA + SWZ((wm * 64 + mt * 16 + a_row) * 128 + a_kb));
#pragma unroll
        for (int q = 0; q < 4; q++)
            ldsm_x4(bfr[0][q], sB + SWZ((wn * 64 + q * 16 + b_row) * 128 + b_kb));

#pragma unroll
        for (int kk = 0; kk < 4; kk++) {
            const int cur = kk & 1, nxt = cur ^ 1;
            if (kk < 3) {   // prefetch kk+1 while kk's MMAs issue
#pragma unroll
                for (int mt = 0; mt < 4; mt++)
                    ldsm_x4(afr[nxt][mt],
                            sA + SWZ((wm * 64 + mt * 16 + a_row) * 128 + (kk + 1) * 32 + a_kb));
#pragma unroll
                for (int q = 0; q < 4; q++)
                    ldsm_x4(bfr[nxt][q],
                            sB + SWZ((wn * 64 + q * 16 + b_row) * 128 + (kk + 1) * 32 + b_kb));
            }
#pragma unroll
            for (int mt = 0; mt < 4; mt++)
#pragma unroll
                for (int nt = 0; nt < 8; nt++) {
                    int q = nt >> 1, h = nt & 1;
                    mma16816(acc[mt][nt], afr[cur][mt], bfr[cur][q][2 * h], bfr[cur][q][2 * h + 1]);
                }
        }
        scur = (scur == 2) ? 0 : scur + 1;
        sload = (sload == 2) ? 0 : sload + 1;
    }
    asm volatile("cp.async.wait_group 0;" ::: "memory");
    __syncthreads();   // pipeline drained; smem reusable for transpose

    // ---- epilogue ----
    const float cb = cov_b[0];
    const int g4 = lane >> 2;
    const int t2 = lane & 3;
    const bool diag = (r == c);

    float* st = (float*)smem;   // 128 x TPITCH transpose buffer (j-major)

#pragma unroll
    for (int mt = 0; mt < 4; mt++)
#pragma unroll
        for (int nt = 0; nt < 8; nt++) {
            int il = wm * 64 + mt * 16 + g4;
            int jl = wn * 64 + nt * 8 + t2 * 2;
            float v0 = acc[mt][nt][0] + cb;
            float v1 = acc[mt][nt][1] + cb;
            float v2 = acc[mt][nt][2] + cb;
            float v3 = acc[mt][nt][3] + cb;

            if (diag) {   // fused diagonal overwrite
                if (il == jl)         v0 = g_d[i0 + il];
                if (il == jl + 1)     v1 = g_d[i0 + il];
                if (il + 8 == jl)     v2 = g_d[i0 + il + 8];
                if (il + 8 == jl + 1) v3 = g_d[i0 + il + 8];
            }

            size_t o0 = (size_t)(i0 + il) * NROWS + (j0 + jl);
            size_t o1 = (size_t)(i0 + il + 8) * NROWS + (j0 + jl);
            *(float2*)(C + o0) = make_float2(v0, v1);
            *(float2*)(C + o1) = make_float2(v2, v3);

            if (!diag) {
                st[(jl + 0) * TPITCH + il]     = v0;
                st[(jl + 1) * TPITCH + il]     = v1;
                st[(jl + 0) * TPITCH + il + 8] = v2;
                st[(jl + 1) * TPITCH + il + 8] = v3;
            }
        }

    if (!diag) {   // mirror 128x128 transposed block into the lower triangle
        __syncthreads();
#pragma unroll
        for (int it = 0; it < 32; it++) {
            int jj = it * 4 + wid;
            float4 v = *(float4*)(st + jj * TPITCH + lane * 4);
            *(float4*)(C + (size_t)(j0 + jj) * NROWS + i0 + lane * 4) = v;
        }
    }
}

// ---------------------------------------------------------------------------
extern "C" void kernel_launch(void* const* d_in, const int* in_sizes, int n_in,
                              void* d_out, int out_size) {
    (void)in_sizes; (void)n_in; (void)out_size;
    const float* x     = (const float*)d_in[0];
    const float* mu_k  = (const float*)d_in[1];
    const float* rho   = (const float*)d_in[2];
    const float* var_k = (const float*)d_in[3];
    const float* mu_b  = (const float*)d_in[4];
    const float* var_b = (const float*)d_in[5];
    const float* cov_b = (const float*)d_in[6];

    float* out = (float*)d_out;
    float* mu  = out;
    float* cov = out + NROWS;

    cudaFuncSetAttribute(cov_gemm_mma, cudaFuncAttributeMaxDynamicSharedMemorySize, SMEM_TOTAL);

    prep_kernel<<<NROWS / 8, 256>>>(x, mu_k, rho, var_k, mu_b, var_b, mu);

    // 2080 = 64*65/2 upper-triangular 128x128 tiles (incl. diagonal)
    cov_gemm_mma<<<2080, 128, SMEM_TOTAL>>>(cov, cov_b);
}